// round 14
// baseline (speedup 1.0000x reference)
#include <cuda_runtime.h>

// img:  (1, 64, 64, 1024) float32
// rois: (1, 1024, 4) int32  -> x, y, w, h
// out:  (1, 1024, 7, 7, 1024) float32
//
// One CTA per (roi-pair, py); 512 threads. Threads 0-255 handle roi 2k,
// threads 256-511 handle roi 2k+1 (one float4 channel lane each).
// Rationale: B300 multi-CTA spread — front-batched LDGs from 4 co-resident
// CTAs contend in the L1tex queue (spr up to ~1.8x at oe=4, MLP_p1~12).
// Fusing 2 ROIs per CTA keeps 32 warps/SM but halves co-resident CTAs
// (oe 4 -> 2), collapsing the spread term. Per-ROI-row work keeps the R11
// block-uniform 3-path dedup (w<=2 / ydup / general), all warp-uniform.

#define POOL 7
#define HW 64
#define CV 256   // float4 lanes per pixel

__device__ __forceinline__ float4 lerp2d(float4 ta, float4 tb, float4 ba, float4 bb,
                                         float wmtx, float wtx, float wmty, float wty)
{
    float4 res;
    res.x = (ta.x * wmtx + tb.x * wtx) * wmty + (ba.x * wmtx + bb.x * wtx) * wty;
    res.y = (ta.y * wmtx + tb.y * wtx) * wmty + (ba.y * wmtx + bb.y * wtx) * wty;
    res.z = (ta.z * wmtx + tb.z * wtx) * wmty + (ba.z * wmtx + bb.z * wtx) * wty;
    res.w = (ta.w * wmtx + tb.w * wtx) * wmty + (ba.w * wmtx + bb.w * wtx) * wty;
    return res;
}

__device__ __forceinline__ float4 sel4(int p, float4 a, float4 b)
{
    float4 r;
    r.x = p ? a.x : b.x;
    r.y = p ? a.y : b.y;
    r.z = p ? a.z : b.z;
    r.w = p ? a.w : b.w;
    return r;
}

__global__ __launch_bounds__(512, 2) void roi_pool_kernel(
    const float* __restrict__ img_,
    const int* __restrict__ rois,
    float* __restrict__ out_)
{
    const float4* __restrict__ img = reinterpret_cast<const float4*>(img_);
    float4* __restrict__ out = reinterpret_cast<float4*>(out_);

    const int py  = blockIdx.x;                          // 0..6
    const int roi = (blockIdx.y << 1) + (threadIdx.x >> 8);  // 0..1023
    const int c   = threadIdx.x & 255;                   // channel float4 lane

    const int4 r = reinterpret_cast<const int4*>(rois)[roi];
    const int rx = r.x, ry = r.y, rw = r.z, rh = r.w;

    // ---- y axis (uniform per half-block) ----
    const float sy   = (float)rh / (float)POOL;
    const float srcy = ((float)py + 0.5f) * sy - 0.5f;
    const float fy   = floorf(srcy);
    const float ty   = srcy - fy;
    const int ylo = min(max((int)fy,     0), rh - 1);
    const int yhi = min(max((int)fy + 1, 0), rh - 1);
    const int noty = (yhi != ylo);

    const float4* __restrict__ rowT = img + (size_t)((ry + ylo) * HW) * CV;
    const float4* __restrict__ rowB = img + (size_t)((ry + yhi) * HW) * CV;

    float4* __restrict__ o = out + ((size_t)roi * (POOL * POOL) + (size_t)py * POOL) * CV + c;

    const float sx   = (float)rw / (float)POOL;
    const float wty  = ty;
    const float wmty = 1.0f - ty;

    // ---- x coords / weights (uniform per half-block, precomputed) ----
    int xA[POOL], xB[POOL];
    float wx[POOL];
    #pragma unroll
    for (int px = 0; px < POOL; px++) {
        const float srcx = ((float)px + 0.5f) * sx - 0.5f;
        const float fx   = floorf(srcx);
        wx[px] = srcx - fx;
        const int xlo = min(max((int)fx,     0), rw - 1);
        const int xhi = min(max((int)fx + 1, 0), rw - 1);
        xA[px] = rx + xlo;
        xB[px] = rx + xhi;
    }

    if (rw <= 2) {
        // ---- path A: at most 2 unique columns: rx and rx+rw-1 ----
        const size_t q0 = (size_t)rx * CV + c;
        const size_t q1 = (size_t)(rx + rw - 1) * CV + c;
        const float4 t0 = __ldg(rowT + q0);
        const float4 t1 = __ldg(rowT + q1);
        float4 b0, b1;
        if (noty) {
            b0 = __ldg(rowB + q0);
            b1 = __ldg(rowB + q1);
        } else {
            b0 = t0;
            b1 = t1;
        }
        #pragma unroll
        for (int px = 0; px < POOL; px++) {
            const float wtx  = wx[px];
            const float wmtx = 1.0f - wtx;
            const int selA = (xA[px] != rx);
            const int selB = (xB[px] != rx);
            const float4 ta = sel4(selA, t1, t0);
            const float4 tb = sel4(selB, t1, t0);
            const float4 ba = sel4(selA, b1, b0);
            const float4 bb = sel4(selB, b1, b0);
            o[px * CV] = lerp2d(ta, tb, ba, bb, wmtx, wtx, wmty, wty);
        }
    } else if (!noty) {
        // ---- path B: bottom row == top row; x-lerp only ----
        #pragma unroll
        for (int px = 0; px < POOL; px++) {
            const float4 ta = __ldg(rowT + (size_t)xA[px] * CV + c);
            const float4 tb = __ldg(rowT + (size_t)xB[px] * CV + c);
            const float wtx  = wx[px];
            const float wmtx = 1.0f - wtx;
            float4 top;
            top.x = ta.x * wmtx + tb.x * wtx;
            top.y = ta.y * wmtx + tb.y * wtx;
            top.z = ta.z * wmtx + tb.z * wtx;
            top.w = ta.w * wmtx + tb.w * wtx;
            float4 res;
            res.x = top.x * wmty + top.x * wty;
            res.y = top.y * wmty + top.y * wty;
            res.z = top.z * wmty + top.z * wty;
            res.w = top.w * wmty + top.w * wty;
            o[px * CV] = res;
        }
    } else {
        // ---- path C: general batched 28-load loop ----
        #pragma unroll
        for (int px = 0; px < POOL; px++) {
            const float4 ta = __ldg(rowT + (size_t)xA[px] * CV + c);
            const float4 tb = __ldg(rowT + (size_t)xB[px] * CV + c);
            const float4 ba = __ldg(rowB + (size_t)xA[px] * CV + c);
            const float4 bb = __ldg(rowB + (size_t)xB[px] * CV + c);
            const float wtx  = wx[px];
            const float wmtx = 1.0f - wtx;
            o[px * CV] = lerp2d(ta, tb, ba, bb, wmtx, wtx, wmty, wty);
        }
    }
}

extern "C" void kernel_launch(void* const* d_in, const int* in_sizes, int n_in,
                              void* d_out, int out_size)
{
    const float* img  = (const float*)d_in[0];
    const int*   rois = (const int*)d_in[1];
    float*       out  = (float*)d_out;

    dim3 grid(POOL, 512);
    roi_pool_kernel<<<grid, 512>>>(img, rois, out);
}